// round 14
// baseline (speedup 1.0000x reference)
#include <cuda_runtime.h>

// Gaussian splatting via tile-owned gather (8x8x16 tiles), precomputed
// per-gaussian exp tables, warp-per-tile accumulate (4 warps / 128-thr CTA).
//  K0 (memset): zero per-tile counters.
//  K1 params: per-gaussian bbox -> packed params.
//  K2 scatter: 18 threads per gaussian, <=1 atomic each; bucket entry =
//     {packed tile-ready window offsets, gid*TABW}.
//  K3 tables: one thread per slot, padded exp tables (coalesced STG).
//     Per gaussian: x[32] y[32] z[48] = 112 floats; zeros outside bbox;
//     intensity folded into z.
//  K4 accum: warp per tile; lane owns (y, z-quarter) slice across all 8 x
//     (16 f32x2 accumulators); tables staged in 32-gaussian chunks into
//     warp-private smem; branchless packed f32x2 scan; coalesced writeout
//     (8 lines per STG op, no staging).

#define NTILES 16384                   // 32 x 32 x 16
#define CAP 64
#define CHUNK 32
#define NMAX 65536
#define TABW 112

__device__ int    d_counts[NTILES];
__device__ int2   d_bucket[NTILES * CAP];   // {offpack, gid*TABW}
__device__ float4 d_params[2 * NMAX];
__device__ float  d_gtab[NMAX * TABW];

__device__ __forceinline__ void fma2(unsigned long long& d,
                                     unsigned long long a,
                                     unsigned long long b) {
    asm("fma.rn.f32x2 %0, %1, %2, %0;" : "+l"(d) : "l"(a), "l"(b));
}
__device__ __forceinline__ unsigned long long mul2(unsigned long long a,
                                                   unsigned long long b) {
    unsigned long long r;
    asm("mul.rn.f32x2 %0, %1, %2;" : "=l"(r) : "l"(a), "l"(b));
    return r;
}
__device__ __forceinline__ unsigned long long dup2(float x) {
    unsigned long long r;
    asm("mov.b64 %0, {%1, %1};" : "=l"(r) : "f"(x));
    return r;
}
__device__ __forceinline__ float2 unpack2(unsigned long long v) {
    float2 r;
    asm("mov.b64 {%0, %1}, %2;" : "=f"(r.x), "=f"(r.y) : "l"(v));
    return r;
}

__global__ void params_kernel(const float* __restrict__ centers,
                              const float* __restrict__ sigmas,
                              const float* __restrict__ intensities,
                              int n) {
    int g = blockIdx.x * blockDim.x + threadIdx.x;
    if (g >= n) return;

    float c3[3];
    c3[0] = __ldg(&centers[3 * g + 0]);
    c3[1] = __ldg(&centers[3 * g + 1]);
    c3[2] = __ldg(&centers[3 * g + 2]);
    const float sig   = __ldg(&sigmas[g]);
    const float inten = __ldg(&intensities[g]);

    const float cut    = 3.0f * sig * 255.0f;
    const float inv2s2 = 0.5f / (sig * sig);

    int mn[3], mx[3];
#pragma unroll
    for (int a = 0; a < 3; a++) {
        float cv = c3[a] * 255.0f;
        mn[a] = (int)floorf(fmaxf(cv - cut, 0.0f));
        mx[a] = (int)fminf(floorf(fminf(cv + cut, 255.0f)) + 1.0f, 256.0f);
    }

    int mnp = mn[0] | (mn[1] << 8) | (mn[2] << 16);
    int wp  = (mx[0] - mn[0]) | ((mx[1] - mn[1]) << 8) | ((mx[2] - mn[2]) << 16);

    d_params[2 * g + 0] = make_float4(c3[0], c3[1], c3[2], inv2s2);
    d_params[2 * g + 1] = make_float4(inten, __int_as_float(mnp), __int_as_float(wp), 0.0f);
}

__global__ void __launch_bounds__(256) scatter_kernel(int n) {
    int e = blockIdx.x * blockDim.x + threadIdx.x;
    int g = e / 18;
    if (g >= n) return;
    int s = e - g * 18;
    int dz = s & 1;
    int q  = s >> 1;
    int dx = q / 3;
    int dy = q - dx * 3;

    float4 p1 = d_params[2 * g + 1];
    int mnp = __float_as_int(p1.y);
    int wp  = __float_as_int(p1.z);
    int mnx = mnp & 255, mny = (mnp >> 8) & 255, mnz = (mnp >> 16) & 255;
    int wx  = wp & 255,  wy  = (wp >> 8) & 255,  wz  = (wp >> 16) & 255;

    int t0x = mnx >> 3, nx = ((mnx + wx - 1) >> 3) - t0x;
    int t0y = mny >> 3, ny = ((mny + wy - 1) >> 3) - t0y;
    int t0z = mnz >> 4, nz = ((mnz + wz - 1) >> 4) - t0z;

    if (dx <= nx && dy <= ny && dz <= nz) {
        int tx = t0x + dx, ty = t0y + dy, tz = t0z + dz;
        int t = (tx << 9) | (ty << 4) | tz;
        int offx = (tx << 3) - mnx + 8;
        int offy = (ty << 3) - mny + 8 + 32;
        int offz = (tz << 4) - mnz + 16 + 64;
        int pack = offx | (offy << 8) | (offz << 16);
        int slot = atomicAdd(&d_counts[t], 1);
        if (slot < CAP) d_bucket[t * CAP + slot] = make_int2(pack, g * TABW);
    }
}

__global__ void table_kernel(int n) {
    int e = blockIdx.x * blockDim.x + threadIdx.x;
    int g = e / TABW;
    if (g >= n) return;
    int s = e - g * TABW;

    float4 p0 = d_params[2 * g + 0];
    float4 p1 = d_params[2 * g + 1];

    int a   = (s < 32) ? 0 : ((s < 64) ? 1 : 2);
    int i   = s - ((a == 0) ? 0 : ((a == 1) ? 32 : 64));
    int pad = (a == 2) ? 16 : 8;

    float c = (a == 0) ? p0.x : ((a == 1) ? p0.y : p0.z);
    int mnp = __float_as_int(p1.y);
    int wp  = __float_as_int(p1.z);
    int mn_a = (mnp >> (8 * a)) & 255;
    int w_a  = (wp  >> (8 * a)) & 255;

    float v = 0.0f;
    if ((unsigned)(i - pad) < (unsigned)w_a) {
        float d = (float)(mn_a - pad + i) * (1.0f / 255.0f) - c;
        v = __expf(-d * d * p0.w);
        if (a == 2) v *= p1.x;
    }
    d_gtab[e] = v;
}

__global__ void __launch_bounds__(128) accum_kernel(float* __restrict__ out) {
    const int wid  = threadIdx.x >> 5;
    const int lane = threadIdx.x & 31;
    const int t = blockIdx.x * 4 + wid;

    const int ox = (t >> 9) << 3;
    const int oy = ((t >> 4) & 31) << 3;
    const int oz = (t & 15) << 4;

    // Warp-private chunked table staging.
    __shared__ int2 sbk[4][CHUNK];
    __shared__ __align__(16) float sx[4][CHUNK * 8];
    __shared__ __align__(16) float sy[4][CHUNK * 8];
    __shared__ __align__(16) float sz[4][CHUNK * 16];

    int2* wbk = sbk[wid];
    float* wx = sx[wid];
    float* wy = sy[wid];
    float* wz = sz[wid];

    int cnt = d_counts[t];
    if (cnt > CAP) cnt = CAP;
    const int bucket_base = t * CAP;

    const int yi = lane >> 2;       // 0..7
    const int zq = lane & 3;        // 0..3 (z quarter)

    unsigned long long accA[8], accB[8];
#pragma unroll
    for (int x = 0; x < 8; x++) { accA[x] = 0ULL; accB[x] = 0ULL; }

    for (int c0 = 0; c0 < cnt; c0 += CHUNK) {
        const int m = min(CHUNK, cnt - c0);

        if (lane < m)
            wbk[lane] = d_bucket[bucket_base + c0 + lane];
        __syncwarp();

        const int m8 = m * 8;
        for (int e = lane; e < m8; e += 32) {
            int g = e >> 3, i = e & 7;
            int2 bk = wbk[g];
            wx[e] = d_gtab[bk.y + (bk.x & 255) + i];
        }
        for (int e = lane; e < m8; e += 32) {
            int g = e >> 3, i = e & 7;
            int2 bk = wbk[g];
            wy[e] = d_gtab[bk.y + ((bk.x >> 8) & 255) + i];
        }
        const int m16 = m * 16;
        for (int e = lane; e < m16; e += 32) {
            int g = e >> 4, i = e & 15;
            int2 bk = wbk[g];
            wz[e] = d_gtab[bk.y + ((bk.x >> 16) & 255) + i];
        }
        __syncwarp();

        // Branchless scan: thread owns (yi, z[4zq..4zq+4)) across all 8 x.
        for (int g = 0; g < m; g++) {
            float syv = wy[g * 8 + yi];
            unsigned long long wyd = dup2(syv);
            ulonglong2 zz = *(const ulonglong2*)&wz[g * 16 + zq * 4];
            unsigned long long tA = mul2(wyd, zz.x);   // sy * (z0, z1)
            unsigned long long tB = mul2(wyd, zz.y);   // sy * (z2, z3)
            float4 xa = *(const float4*)&wx[g * 8];
            float4 xb = *(const float4*)&wx[g * 8 + 4];
            unsigned long long d0 = dup2(xa.x), d1 = dup2(xa.y);
            unsigned long long d2 = dup2(xa.z), d3 = dup2(xa.w);
            unsigned long long d4 = dup2(xb.x), d5 = dup2(xb.y);
            unsigned long long d6 = dup2(xb.z), d7 = dup2(xb.w);
            fma2(accA[0], d0, tA);  fma2(accB[0], d0, tB);
            fma2(accA[1], d1, tA);  fma2(accB[1], d1, tB);
            fma2(accA[2], d2, tA);  fma2(accB[2], d2, tB);
            fma2(accA[3], d3, tA);  fma2(accB[3], d3, tB);
            fma2(accA[4], d4, tA);  fma2(accB[4], d4, tB);
            fma2(accA[5], d5, tA);  fma2(accB[5], d5, tB);
            fma2(accA[6], d6, tA);  fma2(accB[6], d6, tB);
            fma2(accA[7], d7, tA);  fma2(accB[7], d7, tB);
        }
        __syncwarp();
    }

    // Coalesced writeout: per x, warp covers 8 y-rows x 64B of z.
    const int base = ox * 65536 + (oy + yi) * 256 + oz + 4 * zq;
#pragma unroll
    for (int x = 0; x < 8; x++) {
        float2 a = unpack2(accA[x]);
        float2 b = unpack2(accB[x]);
        *(float4*)&out[base + x * 65536] = make_float4(a.x, a.y, b.x, b.y);
    }
}

extern "C" void kernel_launch(void* const* d_in, const int* in_sizes, int n_in,
                              void* d_out, int out_size) {
    const float* centers = (const float*)d_in[0];
    const float* sigmas = (const float*)d_in[1];
    const float* intensities = (const float*)d_in[2];
    float* out = (float*)d_out;
    const int n = in_sizes[1];

    void* counts_ptr = nullptr;
    cudaGetSymbolAddress(&counts_ptr, d_counts);
    cudaMemsetAsync(counts_ptr, 0, NTILES * sizeof(int), 0);

    params_kernel<<<(n + 255) / 256, 256>>>(centers, sigmas, intensities, n);
    scatter_kernel<<<(n * 18 + 255) / 256, 256>>>(n);
    table_kernel<<<(n * TABW + 255) / 256, 256>>>(n);
    accum_kernel<<<NTILES / 4, 128>>>(out);
}

// round 15
// speedup vs baseline: 1.2346x; 1.2346x over previous
#include <cuda_runtime.h>

// Gaussian splatting via tile-owned gather (8x8x16 tiles), precomputed
// per-gaussian exp tables.
//  K0 (memset): zero per-tile counters.
//  K1 scatter: 18 threads per gaussian (bbox recomputed from raw inputs),
//     <=1 atomic each; bucket entry = {packed tile-ready window offsets,
//     gid*TABW}.
//  K2 tables: one thread per slot (bbox recomputed), padded exp tables,
//     coalesced STG. Per gaussian: x[32] y[32] z[48] = 112 floats; x/y
//     anchored mn-8, z anchored mn-16; zeros outside bbox; intensity in z.
//  K3 accum: 64-thread CTA per tile, warps split x (4 slabs each); thread
//     (yi, zq) owns 4x * 4z voxels as 8 f32x2 accumulators. Scan: 1 scalar
//     sy + 1 LDS.128 sz-quarter + 1 broadcast LDS.128 sx-half per gaussian
//     per warp, branchless packed f32x2 FMAs. Writeout: 4 STG.128 per
//     thread, each warp op covers one x-slab (8 lines) - no transpose.

#define NTILES 16384                   // 32 x 32 x 16
#define CAP 64
#define NMAX 65536
#define TABW 112

__device__ int  d_counts[NTILES];
__device__ int2 d_bucket[NTILES * CAP];   // {offpack, gid*TABW}
__device__ float d_gtab[NMAX * TABW];

__device__ __forceinline__ void fma2(unsigned long long& d,
                                     unsigned long long a,
                                     unsigned long long b) {
    asm("fma.rn.f32x2 %0, %1, %2, %0;" : "+l"(d) : "l"(a), "l"(b));
}
__device__ __forceinline__ unsigned long long mul2(unsigned long long a,
                                                   unsigned long long b) {
    unsigned long long r;
    asm("mul.rn.f32x2 %0, %1, %2;" : "=l"(r) : "l"(a), "l"(b));
    return r;
}
__device__ __forceinline__ unsigned long long dup2(float x) {
    unsigned long long r;
    asm("mov.b64 %0, {%1, %1};" : "=l"(r) : "f"(x));
    return r;
}
__device__ __forceinline__ float2 unpack2(unsigned long long v) {
    float2 r;
    asm("mov.b64 {%0, %1}, %2;" : "=f"(r.x), "=f"(r.y) : "l"(v));
    return r;
}

// Shared bbox computation (identical arithmetic everywhere -> identical boxes).
__device__ __forceinline__ void bbox_axis(float c, float cut, int& mn, int& mx) {
    float cv = c * 255.0f;
    mn = (int)floorf(fmaxf(cv - cut, 0.0f));
    mx = (int)fminf(floorf(fminf(cv + cut, 255.0f)) + 1.0f, 256.0f);
}

// 18 threads per gaussian: slot s -> (dx, dy, dz) in 3x3x2.
__global__ void __launch_bounds__(256) scatter_kernel(
        const float* __restrict__ centers,
        const float* __restrict__ sigmas,
        int n) {
    int e = blockIdx.x * blockDim.x + threadIdx.x;
    int g = e / 18;
    if (g >= n) return;
    int s = e - g * 18;
    int dz = s & 1;
    int q  = s >> 1;
    int dx = q / 3;
    int dy = q - dx * 3;

    const float sig = __ldg(&sigmas[g]);
    const float cut = 3.0f * sig * 255.0f;

    int mnx, mxx, mny, mxy, mnz, mxz;
    bbox_axis(__ldg(&centers[3 * g + 0]), cut, mnx, mxx);
    bbox_axis(__ldg(&centers[3 * g + 1]), cut, mny, mxy);
    bbox_axis(__ldg(&centers[3 * g + 2]), cut, mnz, mxz);

    int t0x = mnx >> 3, nx = ((mxx - 1) >> 3) - t0x;
    int t0y = mny >> 3, ny = ((mxy - 1) >> 3) - t0y;
    int t0z = mnz >> 4, nz = ((mxz - 1) >> 4) - t0z;

    if (dx <= nx && dy <= ny && dz <= nz) {
        int tx = t0x + dx, ty = t0y + dy, tz = t0z + dz;
        int t = (tx << 9) | (ty << 4) | tz;
        int offx = (tx << 3) - mnx + 8;
        int offy = (ty << 3) - mny + 8 + 32;
        int offz = (tz << 4) - mnz + 16 + 64;
        int pack = offx | (offy << 8) | (offz << 16);
        int slot = atomicAdd(&d_counts[t], 1);
        if (slot < CAP) d_bucket[t * CAP + slot] = make_int2(pack, g * TABW);
    }
}

// One thread per table slot (112 per gaussian).
__global__ void __launch_bounds__(256) table_kernel(
        const float* __restrict__ centers,
        const float* __restrict__ sigmas,
        const float* __restrict__ intensities,
        int n) {
    int e = blockIdx.x * blockDim.x + threadIdx.x;
    int g = e / TABW;
    if (g >= n) return;
    int s = e - g * TABW;

    int a   = (s < 32) ? 0 : ((s < 64) ? 1 : 2);
    int i   = s - ((a == 0) ? 0 : ((a == 1) ? 32 : 64));
    int pad = (a == 2) ? 16 : 8;

    const float sig    = __ldg(&sigmas[g]);
    const float cut    = 3.0f * sig * 255.0f;
    const float inv2s2 = 0.5f / (sig * sig);
    const float c      = __ldg(&centers[3 * g + a]);

    int mn_a, mx_a;
    bbox_axis(c, cut, mn_a, mx_a);
    int w_a = mx_a - mn_a;

    float v = 0.0f;
    if ((unsigned)(i - pad) < (unsigned)w_a) {
        float d = (float)(mn_a - pad + i) * (1.0f / 255.0f) - c;
        v = __expf(-d * d * inv2s2);
        if (a == 2) v *= __ldg(&intensities[g]);
    }
    d_gtab[e] = v;
}

__global__ void __launch_bounds__(64) accum_kernel(float* __restrict__ out) {
    const int t    = blockIdx.x;
    const int tid  = threadIdx.x;
    const int wid  = tid >> 5;        // warp -> x slab [4*wid, 4*wid+4)
    const int lane = tid & 31;
    const int ox = (t >> 9) << 3;
    const int oy = ((t >> 4) & 31) << 3;
    const int oz = (t & 15) << 4;

    __shared__ int2 sbk[CAP];
    __shared__ __align__(16) float sx[CAP * 8];
    __shared__ __align__(16) float sy[CAP * 8];
    __shared__ __align__(16) float sz[CAP * 16];

    int cnt = d_counts[t];
    if (cnt > CAP) cnt = CAP;
    const int bucket_base = t * CAP;

    for (int i = tid; i < cnt; i += 64)
        sbk[i] = d_bucket[bucket_base + i];
    __syncthreads();

    // Window gathers (tile-ready offsets from scatter; always in-range).
    const int n8 = cnt * 8;
    for (int e = tid; e < n8; e += 64) {
        int g = e >> 3, i = e & 7;
        int2 bk = sbk[g];
        sx[e] = d_gtab[bk.y + (bk.x & 255) + i];
    }
    for (int e = tid; e < n8; e += 64) {
        int g = e >> 3, i = e & 7;
        int2 bk = sbk[g];
        sy[e] = d_gtab[bk.y + ((bk.x >> 8) & 255) + i];
    }
    const int n16 = cnt * 16;
    for (int e = tid; e < n16; e += 64) {
        int g = e >> 4, i = e & 15;
        int2 bk = sbk[g];
        sz[e] = d_gtab[bk.y + ((bk.x >> 16) & 255) + i];
    }
    __syncthreads();

    const int yi = lane >> 2;         // 0..7
    const int zq = lane & 3;          // 0..3 (z quarter)
    const float* syp = &sy[yi];
    const float* szp = &sz[4 * zq];
    const float* sxp = &sx[4 * wid];

    // Thread owns voxels (x in slab, y = yi, z in [4zq, 4zq+4)).
    unsigned long long accL[4], accH[4];
#pragma unroll
    for (int x = 0; x < 4; x++) { accL[x] = 0ULL; accH[x] = 0ULL; }

#pragma unroll 2
    for (int g = 0; g < cnt; g++) {
        float syv = syp[g * 8];
        ulonglong2 zz = *(const ulonglong2*)&szp[g * 16];
        unsigned long long syd = dup2(syv);
        unsigned long long t0 = mul2(syd, zz.x);   // sy * (z0, z1)
        unsigned long long t1 = mul2(syd, zz.y);   // sy * (z2, z3)
        float4 xv = *(const float4*)&sxp[g * 8];
        unsigned long long w;
        w = dup2(xv.x); fma2(accL[0], w, t0); fma2(accH[0], w, t1);
        w = dup2(xv.y); fma2(accL[1], w, t0); fma2(accH[1], w, t1);
        w = dup2(xv.z); fma2(accL[2], w, t0); fma2(accH[2], w, t1);
        w = dup2(xv.w); fma2(accL[3], w, t0); fma2(accH[3], w, t1);
    }

    // Writeout: per x, warp op covers one x-slab (8 y-rows x 64B) = 8 lines.
    const int addr0 = (ox + 4 * wid) * 65536 + (oy + yi) * 256 + oz + 4 * zq;
#pragma unroll
    for (int x = 0; x < 4; x++) {
        float2 lo = unpack2(accL[x]);
        float2 hi = unpack2(accH[x]);
        *(float4*)&out[addr0 + x * 65536] = make_float4(lo.x, lo.y, hi.x, hi.y);
    }
}

extern "C" void kernel_launch(void* const* d_in, const int* in_sizes, int n_in,
                              void* d_out, int out_size) {
    const float* centers = (const float*)d_in[0];
    const float* sigmas = (const float*)d_in[1];
    const float* intensities = (const float*)d_in[2];
    float* out = (float*)d_out;
    const int n = in_sizes[1];

    void* counts_ptr = nullptr;
    cudaGetSymbolAddress(&counts_ptr, d_counts);
    cudaMemsetAsync(counts_ptr, 0, NTILES * sizeof(int), 0);

    scatter_kernel<<<(n * 18 + 255) / 256, 256>>>(centers, sigmas, n);
    table_kernel<<<(n * TABW + 255) / 256, 256>>>(centers, sigmas, intensities, n);
    accum_kernel<<<NTILES, 64>>>(out);
}